// round 2
// baseline (speedup 1.0000x reference)
#include <cuda_runtime.h>
#include <math.h>

#define NTH 256
#define NN  50
#define KA  15
#define KS  35
#define SA  16
#define SS  37

// ---------------- shared memory layout (float offsets) ----------------
#define O_XSX  0                     // 50
#define O_XSY  64                    // 50
#define O_H    128                   // 38*128 = 4864
#define O_SCR  4992                  // 38*512 = 19456 (q/k/v live inside; also ff1; also emb_o; also d2)
#define O_OB   24448                 // 38*128 = 4864
#define O_EA   29312                 // 16*128 = 2048
#define O_KB   31360                 // 16*256 = 4096
#define O_VB   35456                 // 16*256 = 4096
#define O_HDEC 39552                 // 128
#define O_Q2   39680                 // 128
#define O_ODEC 39808                 // 128
#define O_SC   39936                 // 128 (8 heads x 15)
#define O_LG   40064                 // 16
#define O_TCX  40080                 // 40
#define O_TCY  40120                 // 40
#define O_MISC 40160                 // 0:lastx 1:lasty 2:firstx 3:firsty 4:logp
#define O_INT  40168                 // ints: knn[0..34], valid[35..49], mask[50..99]
#define SMEM_FLOATS 40272
#define SMEM_BYTES (SMEM_FLOATS * 4)

struct Params {
    const float* x; const int* start;
    const float *aEmbW, *aEmbB, *aAttnW, *aAttnB, *aW1, *aB1, *aW2, *aB2, *aLn;
    const float *sEmbW, *sEmbB, *sAttnW, *sAttnB, *sW1, *sB1, *sW2, *sB2, *sLn;
    const float *WK, *bK, *WV, *bV, *Wqm, *bqm, *dWq, *dbq, *dWo, *dbo;
    float* out;
};

// GEMM: out[t][colbase+j] = sum_i in[t][i]*W[i][colbase+j] + bias[colbase+j]
// 256 threads: j = tid&127 (output column), half = tid>>7 (token-row group).
template<int S, int DIN, int LDW, bool RELU>
__device__ __forceinline__ void gemm(const float* __restrict__ in, int ldin,
                                     const float* __restrict__ W, int colbase,
                                     const float* __restrict__ bias,
                                     float* __restrict__ out, int ldout)
{
    constexpr int NT = (S + 1) / 2;
    const int j    = threadIdx.x & 127;
    const int half = threadIdx.x >> 7;
    const float* inb = in + half * NT * ldin;
    const float* Wc  = W + colbase + j;
    float acc[NT];
#pragma unroll
    for (int r = 0; r < NT; r++) acc[r] = 0.f;
#pragma unroll 2
    for (int i = 0; i < DIN; i += 4) {
        const float w0 = __ldg(Wc + (i + 0) * LDW);
        const float w1 = __ldg(Wc + (i + 1) * LDW);
        const float w2 = __ldg(Wc + (i + 2) * LDW);
        const float w3 = __ldg(Wc + (i + 3) * LDW);
#pragma unroll
        for (int r = 0; r < NT; r++) {
            const float4 hv = *reinterpret_cast<const float4*>(inb + r * ldin + i);
            acc[r] = fmaf(hv.x, w0, fmaf(hv.y, w1, fmaf(hv.z, w2, fmaf(hv.w, w3, acc[r]))));
        }
    }
    const float bb = bias[colbase + j];
#pragma unroll
    for (int r = 0; r < NT; r++) {
        const int t = half * NT + r;
        if (t < S) {
            float v = acc[r] + bb;
            if (RELU) v = fmaxf(v, 0.f);
            out[t * ldout + colbase + j] = v;
        }
    }
}

// Encoder self-attention. Work item w: head = w&7, qt = w>>3.
// Writes the attention result back into q (each item owns its q slice).
template<int S>
__device__ __forceinline__ void attention(float* __restrict__ q,
                                          const float* __restrict__ k,
                                          const float* __restrict__ v)
{
    for (int w = threadIdx.x; w < 8 * S; w += NTH) {
        const int head = w & 7;
        const int qt   = w >> 3;
        float* qp = q + qt * 128 + head * 16;
        float qr[16];
#pragma unroll
        for (int u = 0; u < 4; u++) {
            float4 t4 = reinterpret_cast<const float4*>(qp)[u];
            qr[4*u+0] = t4.x; qr[4*u+1] = t4.y; qr[4*u+2] = t4.z; qr[4*u+3] = t4.w;
        }
        float sc[S];
        float mx = -INFINITY;
#pragma unroll
        for (int kt = 0; kt < S; kt++) {
            const float4* kp = reinterpret_cast<const float4*>(k + kt * 128 + head * 16);
            float s = 0.f;
#pragma unroll
            for (int u = 0; u < 4; u++) {
                float4 t4 = kp[u];
                s = fmaf(qr[4*u+0], t4.x, s);
                s = fmaf(qr[4*u+1], t4.y, s);
                s = fmaf(qr[4*u+2], t4.z, s);
                s = fmaf(qr[4*u+3], t4.w, s);
            }
            s *= 0.25f;   // 1/sqrt(16)
            sc[kt] = s;
            mx = fmaxf(mx, s);
        }
        float ssum = 0.f;
#pragma unroll
        for (int kt = 0; kt < S; kt++) {
            float e = expf(sc[kt] - mx);
            sc[kt] = e;
            ssum += e;
        }
        const float inv = 1.0f / ssum;
        float ov[16];
#pragma unroll
        for (int d = 0; d < 16; d++) ov[d] = 0.f;
#pragma unroll
        for (int kt = 0; kt < S; kt++) {
            const float pv = sc[kt] * inv;
            const float4* vp = reinterpret_cast<const float4*>(v + kt * 128 + head * 16);
#pragma unroll
            for (int u = 0; u < 4; u++) {
                float4 t4 = vp[u];
                ov[4*u+0] = fmaf(pv, t4.x, ov[4*u+0]);
                ov[4*u+1] = fmaf(pv, t4.y, ov[4*u+1]);
                ov[4*u+2] = fmaf(pv, t4.z, ov[4*u+2]);
                ov[4*u+3] = fmaf(pv, t4.w, ov[4*u+3]);
            }
        }
#pragma unroll
        for (int u = 0; u < 4; u++)
            reinterpret_cast<float4*>(qp)[u] =
                make_float4(ov[4*u+0], ov[4*u+1], ov[4*u+2], ov[4*u+3]);
    }
}

// h[t] = LayerNorm(h[t] + o[t]) with gamma g, beta b. Warp per token.
template<int S>
__device__ __forceinline__ void addln(float* __restrict__ h, const float* __restrict__ o,
                                      const float* __restrict__ g, const float* __restrict__ bt)
{
    const int warp = threadIdx.x >> 5, lane = threadIdx.x & 31;
    for (int t = warp; t < S; t += 8) {
        float r[4];
        float s = 0.f;
#pragma unroll
        for (int u = 0; u < 4; u++) {
            const int j = u * 32 + lane;
            r[u] = h[t * 128 + j] + o[t * 128 + j];
            s += r[u];
        }
#pragma unroll
        for (int off = 16; off; off >>= 1) s += __shfl_xor_sync(0xffffffffu, s, off);
        const float mu = s * (1.0f / 128.0f);
        float vs = 0.f;
#pragma unroll
        for (int u = 0; u < 4; u++) { const float d = r[u] - mu; vs = fmaf(d, d, vs); }
#pragma unroll
        for (int off = 16; off; off >>= 1) vs += __shfl_xor_sync(0xffffffffu, vs, off);
        const float rs = rsqrtf(vs * (1.0f / 128.0f) + 1e-5f);
#pragma unroll
        for (int u = 0; u < 4; u++) {
            const int j = u * 32 + lane;
            h[t * 128 + j] = fmaf(g[j] * (r[u] - mu), rs, bt[j]);
        }
    }
}

// token embedding: h[t][j] = tcx[c]*W[0][j] + tcy[c]*W[1][j] + b[j]
template<int S, bool ACTION>
__device__ __forceinline__ void embed(float* __restrict__ h,
                                      const float* __restrict__ tcx,
                                      const float* __restrict__ tcy,
                                      const float* __restrict__ W,
                                      const float* __restrict__ b)
{
    for (int idx = threadIdx.x; idx < S * 128; idx += NTH) {
        const int t = idx >> 7, j = idx & 127;
        const int c = ACTION ? (t < KA ? t : KS) : t;
        h[idx] = fmaf(tcx[c], __ldg(W + j), fmaf(tcy[c], __ldg(W + 128 + j), __ldg(b + j)));
    }
}

// full 2-layer transformer encoder (pre-embedded h in place)
template<int S>
__device__ __forceinline__ void encode(float* __restrict__ h, float* __restrict__ scr,
                                       float* __restrict__ ob,
                                       const float* attnW, const float* attnB,
                                       const float* W1, const float* b1,
                                       const float* W2, const float* b2,
                                       const float* ln)
{
    float* q = scr;
    float* k = scr + 38 * 128;
    float* v = scr + 2 * 38 * 128;
#pragma unroll 1
    for (int l = 0; l < 2; l++) {
        const float* Wq = attnW + (l * 4 + 0) * 16384;
        const float* Wk = attnW + (l * 4 + 1) * 16384;
        const float* Wv = attnW + (l * 4 + 2) * 16384;
        const float* Wo = attnW + (l * 4 + 3) * 16384;
        const float* bq = attnB + (l * 4 + 0) * 128;
        const float* bk = attnB + (l * 4 + 1) * 128;
        const float* bv = attnB + (l * 4 + 2) * 128;
        const float* bo = attnB + (l * 4 + 3) * 128;

        gemm<S, 128, 128, false>(h, 128, Wq, 0, bq, q, 128);
        gemm<S, 128, 128, false>(h, 128, Wk, 0, bk, k, 128);
        gemm<S, 128, 128, false>(h, 128, Wv, 0, bv, v, 128);
        __syncthreads();
        attention<S>(q, k, v);
        __syncthreads();
        gemm<S, 128, 128, false>(q, 128, Wo, 0, bo, ob, 128);
        __syncthreads();
        addln<S>(h, ob, ln + (l * 2 + 0) * 256, ln + (l * 2 + 0) * 256 + 128);
        __syncthreads();
        // FF
        gemm<S, 128, 512, true>(h, 128, W1 + l * 65536, 0,   b1 + l * 512, scr, 512);
        gemm<S, 128, 512, true>(h, 128, W1 + l * 65536, 128, b1 + l * 512, scr, 512);
        gemm<S, 128, 512, true>(h, 128, W1 + l * 65536, 256, b1 + l * 512, scr, 512);
        gemm<S, 128, 512, true>(h, 128, W1 + l * 65536, 384, b1 + l * 512, scr, 512);
        __syncthreads();
        gemm<S, 512, 128, false>(scr, 512, W2 + l * 65536, 0, b2 + l * 128, ob, 128);
        __syncthreads();
        addln<S>(h, ob, ln + (l * 2 + 1) * 256, ln + (l * 2 + 1) * 256 + 128);
        __syncthreads();
    }
}

extern __shared__ float sm[];

__global__ void __launch_bounds__(NTH, 1) tsp_kernel(Params p)
{
    const int b = blockIdx.x, tid = threadIdx.x;
    const int B = gridDim.x;

    float* xsx  = sm + O_XSX;
    float* xsy  = sm + O_XSY;
    float* h    = sm + O_H;
    float* scr  = sm + O_SCR;
    float* ob   = sm + O_OB;
    float* ea   = sm + O_EA;
    float* Kb   = sm + O_KB;
    float* Vb   = sm + O_VB;
    float* hdec = sm + O_HDEC;
    float* q2   = sm + O_Q2;
    float* odec = sm + O_ODEC;
    float* sc   = sm + O_SC;
    float* lg   = sm + O_LG;
    float* tcx  = sm + O_TCX;
    float* tcy  = sm + O_TCY;
    float* misc = sm + O_MISC;
    int* knn   = (int*)(sm + O_INT);
    int* valid = knn + 35;
    int* mask  = knn + 50;

    for (int n = tid; n < NN; n += NTH) {
        xsx[n] = p.x[(b * NN + n) * 2 + 0];
        xsy[n] = p.x[(b * NN + n) * 2 + 1];
        mask[n] = 1;
    }
    __syncthreads();
    if (tid == 0) {
        const int st = p.start[b];
        mask[st] = 0;
        misc[0] = xsx[st]; misc[1] = xsy[st];   // last
        misc[2] = xsx[st]; misc[3] = xsy[st];   // first
        misc[4] = 0.f;                          // logp
        p.out[b * NN] = (float)st;
    }
    __syncthreads();

    for (int step = 0; step < NN - 1; step++) {
        const float lastx = misc[0], lasty = misc[1];

        // ---- squared distances (masked -> BIG) ----
        float* d2 = scr;
        if (tid < NN) {
            const float dx = xsx[tid] - lastx, dy = xsy[tid] - lasty;
            d2[tid] = mask[tid] ? (dx * dx + dy * dy) : 1e9f;
        }
        __syncthreads();

        // ---- top-35 smallest (d2, idx) via warp min-reduction; jax tie order ----
        if (tid < 32) {
            unsigned long long k0 = ~0ull, k1 = ~0ull;
            if (tid < NN)      k0 = (((unsigned long long)__float_as_uint(d2[tid]))     << 32) | (unsigned)tid;
            if (tid + 32 < NN) k1 = (((unsigned long long)__float_as_uint(d2[tid + 32])) << 32) | (unsigned)(tid + 32);
            for (int r = 0; r < KS; r++) {
                unsigned long long m = k0 < k1 ? k0 : k1;
#pragma unroll
                for (int off = 16; off; off >>= 1) {
                    unsigned long long o = __shfl_xor_sync(0xffffffffu, m, off);
                    if (o < m) m = o;
                }
                if (k0 == m) k0 = ~0ull;
                if (k1 == m) k1 = ~0ull;
                if (tid == 0) knn[r] = (int)(m & 0xffffffffull);
            }
        }
        __syncthreads();

        if (tid < KS) { const int n = knn[tid]; tcx[tid] = xsx[n]; tcy[tid] = xsy[n]; }
        if (tid < KA) valid[tid] = mask[knn[tid]];
        if (tid == 0) { tcx[35] = lastx; tcy[35] = lasty; tcx[36] = misc[2]; tcy[36] = misc[3]; }
        __syncthreads();

        // ---- ACTION encoder (16 tokens) ----
        embed<SA, true>(h, tcx, tcy, p.aEmbW, p.aEmbB);
        __syncthreads();
        encode<SA>(h, scr, ob, p.aAttnW, p.aAttnB, p.aW1, p.aB1, p.aW2, p.aB2, p.aLn);
        for (int i = tid; i < SA * 128; i += NTH) ea[i] = h[i];
        __syncthreads();

        // ---- STATE encoder (37 tokens) ----
        embed<SS, false>(h, tcx, tcy, p.sEmbW, p.sEmbB);
        __syncthreads();
        encode<SS>(h, scr, ob, p.sAttnW, p.sAttnB, p.sW1, p.sB1, p.sW2, p.sB2, p.sLn);

        // ---- build emb_o = [emb_a_j | emb_s_j], 15 x 256 (row 15 zero-pad) ----
        for (int idx = tid; idx < KA * 256; idx += NTH) {
            const int j = idx >> 8, c = idx & 255;
            scr[idx] = (c < 128) ? ea[j * 128 + c] : h[j * 128 + (c - 128)];
        }
        for (int idx = tid; idx < 256; idx += NTH) scr[KA * 256 + idx] = 0.f;
        __syncthreads();

        // ---- h_dec = emb_q @ Wq_mlp + bq_mlp  (384 -> 128) ----
        if (tid < 128) {
            float a = __ldg(p.bqm + tid);
            for (int i = 0; i < 128; i++) a = fmaf(ea[15 * 128 + i], __ldg(p.Wqm + i * 128 + tid), a);
            for (int i = 0; i < 128; i++) a = fmaf(h[35 * 128 + i], __ldg(p.Wqm + (128 + i) * 128 + tid), a);
            for (int i = 0; i < 128; i++) a = fmaf(h[36 * 128 + i], __ldg(p.Wqm + (256 + i) * 128 + tid), a);
            hdec[tid] = a;
        }
        // ---- K, V projections (emb_o @ WK/WV): K both halves, V only l=0 half ----
        gemm<KA, 256, 256, false>(scr, 256, p.WK, 0,   p.bK, Kb, 256);
        gemm<KA, 256, 256, false>(scr, 256, p.WK, 128, p.bK, Kb, 256);
        gemm<KA, 256, 256, false>(scr, 256, p.WV, 0,   p.bV, Vb, 256);
        __syncthreads();

        // ---- decoder layer 0 (MHA over 15 actions) ----
        if (tid < 128) {
            float a = __ldg(p.dbq + tid);
            for (int i = 0; i < 128; i++) a = fmaf(hdec[i], __ldg(p.dWq + i * 128 + tid), a);
            q2[tid] = a;
        }
        __syncthreads();
        if (tid < 120) {
            const int head = tid & 7, kk = tid >> 3;
            float s = 0.f;
            const float* kp = Kb + kk * 256 + head * 16;
#pragma unroll
            for (int d = 0; d < 16; d++) s = fmaf(q2[head * 16 + d], kp[d], s);
            s *= 0.25f;
            sc[head * 15 + kk] = valid[kk] ? s : -1e9f;
        }
        __syncthreads();
        if (tid < 8) {
            float mx = -INFINITY;
            for (int kk = 0; kk < KA; kk++) mx = fmaxf(mx, sc[tid * 15 + kk]);
            float ssum = 0.f;
            for (int kk = 0; kk < KA; kk++) {
                const float e = expf(sc[tid * 15 + kk] - mx);
                sc[tid * 15 + kk] = e;
                ssum += e;
            }
            const float inv = 1.0f / ssum;
            for (int kk = 0; kk < KA; kk++) sc[tid * 15 + kk] *= inv;
        }
        __syncthreads();
        if (tid < 128) {
            const int head = tid >> 4, d = tid & 15;
            float o = 0.f;
            for (int kk = 0; kk < KA; kk++)
                o = fmaf(sc[head * 15 + kk], Vb[kk * 256 + head * 16 + d], o);
            odec[tid] = o;
        }
        __syncthreads();
        if (tid < 128) {
            float a = __ldg(p.dbo + tid);
            for (int i = 0; i < 128; i++) a = fmaf(odec[i], __ldg(p.dWo + i * 128 + tid), a);
            hdec[tid] += a;
        }
        __syncthreads();

        // ---- final pointer layer ----
        if (tid < 128) {
            float a = __ldg(p.dbq + 128 + tid);
            for (int i = 0; i < 128; i++) a = fmaf(hdec[i], __ldg(p.dWq + 16384 + i * 128 + tid), a);
            q2[tid] = a;
        }
        __syncthreads();
        if (tid < KA) {
            float s = 0.f;
            const float* kp = Kb + tid * 256 + 128;
            for (int d = 0; d < 128; d++) s = fmaf(q2[d], kp[d], s);
            s *= 0.08838834764831845f;   // 1/sqrt(128)
            s = 10.0f * tanhf(s);
            lg[tid] = valid[tid] ? s : -1e9f;
        }
        __syncthreads();
        if (tid == 0) {
            float mx = -INFINITY; int best = 0;
            for (int kk = 0; kk < KA; kk++)
                if (lg[kk] > mx) { mx = lg[kk]; best = kk; }
            float ssum = 0.f, eb = 0.f;
            for (int kk = 0; kk < KA; kk++) {
                const float e = expf(lg[kk] - mx);
                ssum += e;
                if (kk == best) eb = e;
            }
            misc[4] += logf(eb / ssum);
            const int nxt = knn[best];
            mask[nxt] = 0;
            misc[0] = xsx[nxt]; misc[1] = xsy[nxt];
            p.out[b * NN + step + 1] = (float)nxt;
        }
        __syncthreads();
    }

    if (tid == 0) p.out[B * NN + b] = misc[4];
}

extern "C" void kernel_launch(void* const* d_in, const int* in_sizes, int n_in,
                              void* d_out, int out_size)
{
    // input index base: skip action_k/state_k scalars if present
    int i = 2;
    if (n_in > 2 && in_sizes[2] == 1) i = 4;

    Params p;
    p.x     = (const float*)d_in[0];
    p.start = (const int*)d_in[1];
    p.aEmbW  = (const float*)d_in[i++];  p.aEmbB  = (const float*)d_in[i++];
    p.aAttnW = (const float*)d_in[i++];  p.aAttnB = (const float*)d_in[i++];
    p.aW1    = (const float*)d_in[i++];  p.aB1    = (const float*)d_in[i++];
    p.aW2    = (const float*)d_in[i++];  p.aB2    = (const float*)d_in[i++];
    p.aLn    = (const float*)d_in[i++];
    p.sEmbW  = (const float*)d_in[i++];  p.sEmbB  = (const float*)d_in[i++];
    p.sAttnW = (const float*)d_in[i++];  p.sAttnB = (const float*)d_in[i++];
    p.sW1    = (const float*)d_in[i++];  p.sB1    = (const float*)d_in[i++];
    p.sW2    = (const float*)d_in[i++];  p.sB2    = (const float*)d_in[i++];
    p.sLn    = (const float*)d_in[i++];
    p.WK  = (const float*)d_in[i++];  p.bK  = (const float*)d_in[i++];
    p.WV  = (const float*)d_in[i++];  p.bV  = (const float*)d_in[i++];
    p.Wqm = (const float*)d_in[i++];  p.bqm = (const float*)d_in[i++];
    p.dWq = (const float*)d_in[i++];  p.dbq = (const float*)d_in[i++];
    p.dWo = (const float*)d_in[i++];  p.dbo = (const float*)d_in[i++];
    p.out = (float*)d_out;

    cudaFuncSetAttribute(tsp_kernel, cudaFuncAttributeMaxDynamicSharedMemorySize, SMEM_BYTES);

    const int B = in_sizes[1];   // start_idx element count = batch
    tsp_kernel<<<B, NTH, SMEM_BYTES>>>(p);
}

// round 3
// speedup vs baseline: 1.3420x; 1.3420x over previous
#include <cuda_runtime.h>
#include <math.h>

#define NTH 512
#define NN  50
#define KA  15
#define KS  35
#define SA  16
#define SS  37

// ---------------- transposed-weight scratch (quad-interleaved) ----------------
// layout per matrix [R][C]:  wt[(r>>2)*4C + c*4 + (r&3)] = W[r][c]
#define OFF_AATTN 0
#define OFF_SATTN 131072
#define OFF_AW1   262144
#define OFF_SW1   393216
#define OFF_AW2   524288
#define OFF_SW2   655360
#define OFF_WK    786432
#define OFF_WV    851968
#define OFF_WQM   917504
#define OFF_DWQ   966656
#define OFF_DWO   999424
#define WT_TOTAL  1032192

__device__ float g_wt[WT_TOTAL];

// ---------------- shared memory layout (float offsets) ----------------
#define O_XSX  0
#define O_XSY  64
#define O_H    128        // 40x128 interleaved = 5120
#define O_SCR  5248       // 20480: q(lin)@+0, k(lin)@+5120, v(lin)@+10240, ao(int)@+15360; ff int 512; emb_o int 256; d2
#define O_OB   25728      // 40x128 linear = 5120
#define O_EA   30848      // 16x128 interleaved = 2048
#define O_KB   32896      // 16x256 linear = 4096
#define O_VB   36992      // 16x128 linear = 2048
#define O_EQ   39040      // 384
#define O_HDEC 39424
#define O_Q2   39552
#define O_ODEC 39680
#define O_SCT  39808
#define O_LG   39936
#define O_TCX  39952
#define O_TCY  39992
#define O_MISC 40032
#define O_INT  40040
#define SMEM_FLOATS 40144
#define SMEM_BYTES (SMEM_FLOATS * 4)

struct Params {
    const float* x; const int* start;
    const float *aEmbW, *aEmbB, *aAttnB, *aB1, *aB2, *aLn;
    const float *sEmbW, *sEmbB, *sAttnB, *sB1, *sB2, *sLn;
    const float *bK, *bV, *bqm, *dbq, *dbo;
    float* out;
};

// ---------------- weight transpose prologue ----------------
__global__ void tq_kernel(const float* __restrict__ src, int dstOff, int R, int C, int nmat)
{
    const int total = nmat * R * C;
    for (int idx = blockIdx.x * blockDim.x + threadIdx.x; idx < total;
         idx += gridDim.x * blockDim.x) {
        const int m = idx / (R * C);
        const int rem = idx - m * R * C;
        const int r = rem / C;
        const int c = rem - r * C;
        g_wt[dstOff + m * R * C + (r >> 2) * (4 * C) + c * 4 + (r & 3)] = src[idx];
    }
}

// ---------------- packed-f32x2 GEMM ----------------
// in: row-pair-interleaved activations (pair p, dim i) at in[p*2*DIN + 2*i + lane]
// wt: quad-interleaved transposed weights, CTOT total columns
// out: LINOUT ? linear [t][outCols] : interleaved [pair][2*outCols]
template<int PAIRS, int DIN, int CTOT, bool RELU, bool LINOUT>
__device__ __forceinline__ void gemmP(const float* __restrict__ in,
                                      const float* __restrict__ wt,
                                      const float* __restrict__ bias, int colbase,
                                      float* __restrict__ out, int outCols)
{
    constexpr int PPG = PAIRS / 4;
    const int j = threadIdx.x & 127;
    const int g = threadIdx.x >> 7;
    const float* inb = in + g * PPG * 2 * DIN;
    const float4* wq = reinterpret_cast<const float4*>(wt) + (colbase + j);
    unsigned long long acc[PPG];
#pragma unroll
    for (int p = 0; p < PPG; p++) acc[p] = 0ull;
#pragma unroll 2
    for (int i = 0; i < DIN; i += 4) {
        const float4 w = __ldg(wq + (i >> 2) * CTOT);
        unsigned long long w0, w1, w2, w3;
        asm("mov.b64 %0,{%1,%1};" : "=l"(w0) : "f"(w.x));
        asm("mov.b64 %0,{%1,%1};" : "=l"(w1) : "f"(w.y));
        asm("mov.b64 %0,{%1,%1};" : "=l"(w2) : "f"(w.z));
        asm("mov.b64 %0,{%1,%1};" : "=l"(w3) : "f"(w.w));
#pragma unroll
        for (int p = 0; p < PPG; p++) {
            const ulonglong2* ip =
                reinterpret_cast<const ulonglong2*>(inb + p * 2 * DIN + 2 * i);
            const ulonglong2 a01 = ip[0];
            const ulonglong2 a23 = ip[1];
            asm("fma.rn.f32x2 %0, %1, %2, %0;" : "+l"(acc[p]) : "l"(a01.x), "l"(w0));
            asm("fma.rn.f32x2 %0, %1, %2, %0;" : "+l"(acc[p]) : "l"(a01.y), "l"(w1));
            asm("fma.rn.f32x2 %0, %1, %2, %0;" : "+l"(acc[p]) : "l"(a23.x), "l"(w2));
            asm("fma.rn.f32x2 %0, %1, %2, %0;" : "+l"(acc[p]) : "l"(a23.y), "l"(w3));
        }
    }
    const float bb = __ldg(bias + colbase + j);
#pragma unroll
    for (int p = 0; p < PPG; p++) {
        float lo, hi;
        asm("mov.b64 {%0,%1}, %2;" : "=f"(lo), "=f"(hi) : "l"(acc[p]));
        lo += bb; hi += bb;
        if (RELU) { lo = fmaxf(lo, 0.f); hi = fmaxf(hi, 0.f); }
        const int pr = g * PPG + p;
        if (LINOUT) {
            out[(2 * pr + 0) * outCols + colbase + j] = lo;
            out[(2 * pr + 1) * outCols + colbase + j] = hi;
        } else {
            *reinterpret_cast<float2*>(out + pr * 2 * outCols + 2 * (colbase + j)) =
                make_float2(lo, hi);
        }
    }
}

// ---------------- encoder self-attention ----------------
// q,k,v: LINEAR [t][128].  ao: interleaved output.
template<int S>
__device__ __forceinline__ void attnP(const float* __restrict__ q,
                                      const float* __restrict__ k,
                                      const float* __restrict__ v,
                                      float* __restrict__ ao)
{
    for (int w = threadIdx.x; w < 8 * S; w += NTH) {
        const int head = w & 7;
        const int qt   = w >> 3;
        const float* qp = q + qt * 128 + head * 16;
        float qr[16];
#pragma unroll
        for (int u = 0; u < 4; u++) {
            float4 t4 = reinterpret_cast<const float4*>(qp)[u];
            qr[4*u+0] = t4.x; qr[4*u+1] = t4.y; qr[4*u+2] = t4.z; qr[4*u+3] = t4.w;
        }
        float sc[S];
        float mx = -INFINITY;
#pragma unroll
        for (int kt = 0; kt < S; kt++) {
            const float4* kp = reinterpret_cast<const float4*>(k + kt * 128 + head * 16);
            float s = 0.f;
#pragma unroll
            for (int u = 0; u < 4; u++) {
                float4 t4 = kp[u];
                s = fmaf(qr[4*u+0], t4.x, s);
                s = fmaf(qr[4*u+1], t4.y, s);
                s = fmaf(qr[4*u+2], t4.z, s);
                s = fmaf(qr[4*u+3], t4.w, s);
            }
            s *= 0.25f;
            sc[kt] = s;
            mx = fmaxf(mx, s);
        }
        float ssum = 0.f;
#pragma unroll
        for (int kt = 0; kt < S; kt++) {
            float e = expf(sc[kt] - mx);
            sc[kt] = e;
            ssum += e;
        }
        const float inv = 1.0f / ssum;
        float ov[16];
#pragma unroll
        for (int d = 0; d < 16; d++) ov[d] = 0.f;
#pragma unroll
        for (int kt = 0; kt < S; kt++) {
            const float pv = sc[kt] * inv;
            const float4* vp = reinterpret_cast<const float4*>(v + kt * 128 + head * 16);
#pragma unroll
            for (int u = 0; u < 4; u++) {
                float4 t4 = vp[u];
                ov[4*u+0] = fmaf(pv, t4.x, ov[4*u+0]);
                ov[4*u+1] = fmaf(pv, t4.y, ov[4*u+1]);
                ov[4*u+2] = fmaf(pv, t4.z, ov[4*u+2]);
                ov[4*u+3] = fmaf(pv, t4.w, ov[4*u+3]);
            }
        }
        float* aop = ao + (qt >> 1) * 256 + (qt & 1) + 2 * head * 16;
#pragma unroll
        for (int d = 0; d < 16; d++) aop[2 * d] = ov[d];
    }
}

// h (interleaved) = LN(h + ob(linear)).  warp per token.
template<int S>
__device__ __forceinline__ void addln(float* __restrict__ h, const float* __restrict__ ob,
                                      const float* __restrict__ g, const float* __restrict__ bt)
{
    const int warp = threadIdx.x >> 5, lane = threadIdx.x & 31;
    for (int t = warp; t < S; t += 16) {
        float* hp = h + (t >> 1) * 256 + (t & 1);
        const float* op = ob + t * 128;
        float r[4];
        float s = 0.f;
#pragma unroll
        for (int u = 0; u < 4; u++) {
            const int j = u * 32 + lane;
            r[u] = hp[2 * j] + op[j];
            s += r[u];
        }
#pragma unroll
        for (int off = 16; off; off >>= 1) s += __shfl_xor_sync(0xffffffffu, s, off);
        const float mu = s * (1.0f / 128.0f);
        float vs = 0.f;
#pragma unroll
        for (int u = 0; u < 4; u++) { const float d = r[u] - mu; vs = fmaf(d, d, vs); }
#pragma unroll
        for (int off = 16; off; off >>= 1) vs += __shfl_xor_sync(0xffffffffu, vs, off);
        const float rs = rsqrtf(vs * (1.0f / 128.0f) + 1e-5f);
#pragma unroll
        for (int u = 0; u < 4; u++) {
            const int j = u * 32 + lane;
            hp[2 * j] = fmaf(g[j] * (r[u] - mu), rs, bt[j]);
        }
    }
}

// token embedding into interleaved h; pad rows zeroed
template<int S, int PADS, bool ACTION>
__device__ __forceinline__ void embed(float* __restrict__ h,
                                      const float* __restrict__ tcx,
                                      const float* __restrict__ tcy,
                                      const float* __restrict__ W,
                                      const float* __restrict__ b)
{
    for (int idx = threadIdx.x; idx < PADS * 128; idx += NTH) {
        const int t = idx >> 7, j = idx & 127;
        float val = 0.f;
        if (t < S) {
            const int c = ACTION ? (t < KA ? t : KS) : t;
            val = fmaf(tcx[c], __ldg(W + j), fmaf(tcy[c], __ldg(W + 128 + j), __ldg(b + j)));
        }
        h[(t >> 1) * 256 + 2 * j + (t & 1)] = val;
    }
}

// 2-layer encoder; h interleaved (PADS rows)
template<int S>
__device__ __forceinline__ void encode(float* __restrict__ h, float* __restrict__ scr,
                                       float* __restrict__ ob,
                                       int attnOff, const float* attnB,
                                       int w1Off, const float* b1,
                                       int w2Off, const float* b2,
                                       const float* ln)
{
    constexpr int PADS  = (S + 7) & ~7;
    constexpr int PAIRS = PADS / 2;
    float* q  = scr;
    float* k  = scr + 5120;
    float* v  = scr + 10240;
    float* ao = scr + 15360;
#pragma unroll 1
    for (int l = 0; l < 2; l++) {
        const float* Wq = g_wt + attnOff + (l * 4 + 0) * 16384;
        const float* Wk = g_wt + attnOff + (l * 4 + 1) * 16384;
        const float* Wv = g_wt + attnOff + (l * 4 + 2) * 16384;
        const float* Wo = g_wt + attnOff + (l * 4 + 3) * 16384;
        const float* bq = attnB + (l * 4 + 0) * 128;
        const float* bk = attnB + (l * 4 + 1) * 128;
        const float* bv = attnB + (l * 4 + 2) * 128;
        const float* bo = attnB + (l * 4 + 3) * 128;

        gemmP<PAIRS, 128, 128, false, true>(h, Wq, bq, 0, q, 128);
        gemmP<PAIRS, 128, 128, false, true>(h, Wk, bk, 0, k, 128);
        gemmP<PAIRS, 128, 128, false, true>(h, Wv, bv, 0, v, 128);
        __syncthreads();
        attnP<S>(q, k, v, ao);
        __syncthreads();
        gemmP<PAIRS, 128, 128, false, true>(ao, Wo, bo, 0, ob, 128);
        __syncthreads();
        addln<S>(h, ob, ln + (l * 2 + 0) * 256, ln + (l * 2 + 0) * 256 + 128);
        __syncthreads();
        gemmP<PAIRS, 128, 512, true, false>(h, g_wt + w1Off + l * 65536, b1 + l * 512, 0,   scr, 512);
        gemmP<PAIRS, 128, 512, true, false>(h, g_wt + w1Off + l * 65536, b1 + l * 512, 128, scr, 512);
        gemmP<PAIRS, 128, 512, true, false>(h, g_wt + w1Off + l * 65536, b1 + l * 512, 256, scr, 512);
        gemmP<PAIRS, 128, 512, true, false>(h, g_wt + w1Off + l * 65536, b1 + l * 512, 384, scr, 512);
        __syncthreads();
        gemmP<PAIRS, 512, 128, false, true>(scr, g_wt + w2Off + l * 65536, b2 + l * 128, 0, ob, 128);
        __syncthreads();
        addln<S>(h, ob, ln + (l * 2 + 1) * 256, ln + (l * 2 + 1) * 256 + 128);
        __syncthreads();
    }
}

extern __shared__ float sm[];

__global__ void __launch_bounds__(NTH, 1) tsp_kernel(Params p)
{
    const int b = blockIdx.x, tid = threadIdx.x;
    const int B = gridDim.x;

    float* xsx  = sm + O_XSX;
    float* xsy  = sm + O_XSY;
    float* h    = sm + O_H;
    float* scr  = sm + O_SCR;
    float* ob   = sm + O_OB;
    float* ea   = sm + O_EA;
    float* Kb   = sm + O_KB;
    float* Vb   = sm + O_VB;
    float* eq   = sm + O_EQ;
    float* hdec = sm + O_HDEC;
    float* q2   = sm + O_Q2;
    float* odec = sm + O_ODEC;
    float* sc   = sm + O_SCT;
    float* lg   = sm + O_LG;
    float* tcx  = sm + O_TCX;
    float* tcy  = sm + O_TCY;
    float* misc = sm + O_MISC;
    int* knn   = (int*)(sm + O_INT);
    int* valid = knn + 35;
    int* mask  = knn + 50;

    for (int n = tid; n < NN; n += NTH) {
        xsx[n] = p.x[(b * NN + n) * 2 + 0];
        xsy[n] = p.x[(b * NN + n) * 2 + 1];
        mask[n] = 1;
    }
    __syncthreads();
    if (tid == 0) {
        const int st = p.start[b];
        mask[st] = 0;
        misc[0] = xsx[st]; misc[1] = xsy[st];
        misc[2] = xsx[st]; misc[3] = xsy[st];
        misc[4] = 0.f;
        p.out[b * NN] = (float)st;
    }
    __syncthreads();

    for (int step = 0; step < NN - 1; step++) {
        const float lastx = misc[0], lasty = misc[1];

        float* d2 = scr;
        if (tid < NN) {
            const float dx = xsx[tid] - lastx, dy = xsy[tid] - lasty;
            d2[tid] = mask[tid] ? (dx * dx + dy * dy) : 1e9f;
        }
        __syncthreads();

        // top-35 smallest (d2, idx), jax tie order
        if (tid < 32) {
            unsigned long long k0 = ~0ull, k1 = ~0ull;
            if (tid < NN)      k0 = (((unsigned long long)__float_as_uint(d2[tid]))      << 32) | (unsigned)tid;
            if (tid + 32 < NN) k1 = (((unsigned long long)__float_as_uint(d2[tid + 32])) << 32) | (unsigned)(tid + 32);
            for (int r = 0; r < KS; r++) {
                unsigned long long m = k0 < k1 ? k0 : k1;
#pragma unroll
                for (int off = 16; off; off >>= 1) {
                    unsigned long long o = __shfl_xor_sync(0xffffffffu, m, off);
                    if (o < m) m = o;
                }
                if (k0 == m) k0 = ~0ull;
                if (k1 == m) k1 = ~0ull;
                if (tid == 0) knn[r] = (int)(m & 0xffffffffull);
            }
        }
        __syncthreads();

        if (tid < KS) { const int n = knn[tid]; tcx[tid] = xsx[n]; tcy[tid] = xsy[n]; }
        if (tid < KA) valid[tid] = mask[knn[tid]];
        if (tid == 0) { tcx[35] = lastx; tcy[35] = lasty; tcx[36] = misc[2]; tcy[36] = misc[3]; }
        __syncthreads();

        // ---- ACTION encoder (16 tokens) ----
        embed<SA, 16, true>(h, tcx, tcy, p.aEmbW, p.aEmbB);
        __syncthreads();
        encode<SA>(h, scr, ob, OFF_AATTN, p.aAttnB, OFF_AW1, p.aB1, OFF_AW2, p.aB2, p.aLn);
        for (int i = tid; i < 2048; i += NTH) ea[i] = h[i];   // rows 0..15 verbatim
        __syncthreads();

        // ---- STATE encoder (37 tokens) ----
        embed<SS, 40, false>(h, tcx, tcy, p.sEmbW, p.sEmbB);
        __syncthreads();
        encode<SS>(h, scr, ob, OFF_SATTN, p.sAttnB, OFF_SW1, p.sB1, OFF_SW2, p.sB2, p.sLn);

        // ---- emb_o (interleaved, 16 rows x 256; row 15 zero) + eq linear ----
        for (int idx = tid; idx < 16 * 256; idx += NTH) {
            const int row = idx >> 8, c = idx & 255;
            float val = 0.f;
            if (row < KA) {
                val = (c < 128) ? ea[(row >> 1) * 256 + 2 * c + (row & 1)]
                                : h[(row >> 1) * 256 + 2 * (c - 128) + (row & 1)];
            }
            scr[(row >> 1) * 512 + 2 * c + (row & 1)] = val;
        }
        if (tid < 128) {
            eq[tid]       = ea[7 * 256 + 2 * tid + 1];   // ea row 15
            eq[128 + tid] = h[17 * 256 + 2 * tid + 1];   // h row 35
            eq[256 + tid] = h[18 * 256 + 2 * tid + 0];   // h row 36
        }
        __syncthreads();

        // ---- h_dec = emb_q @ Wq_mlp + bq_mlp ----
        if (tid < 128) {
            float a = __ldg(p.bqm + tid);
            const float4* wq = reinterpret_cast<const float4*>(g_wt + OFF_WQM) + tid;
            for (int i = 0; i < 384; i += 4) {
                const float4 w = __ldg(wq + (i >> 2) * 128);
                a = fmaf(eq[i], w.x, fmaf(eq[i+1], w.y, fmaf(eq[i+2], w.z, fmaf(eq[i+3], w.w, a))));
            }
            hdec[tid] = a;
        }
        // ---- K (256 cols) & V (first 128 cols) ----
        gemmP<8, 256, 256, false, true>(scr, g_wt + OFF_WK, p.bK, 0,   Kb, 256);
        gemmP<8, 256, 256, false, true>(scr, g_wt + OFF_WK, p.bK, 128, Kb, 256);
        gemmP<8, 256, 256, false, true>(scr, g_wt + OFF_WV, p.bV, 0,   Vb, 128);
        __syncthreads();

        // ---- decoder layer 0 (MHA over 15 actions) ----
        if (tid < 128) {
            float a = __ldg(p.dbq + tid);
            const float4* wq = reinterpret_cast<const float4*>(g_wt + OFF_DWQ) + tid;
            for (int i = 0; i < 128; i += 4) {
                const float4 w = __ldg(wq + (i >> 2) * 128);
                a = fmaf(hdec[i], w.x, fmaf(hdec[i+1], w.y, fmaf(hdec[i+2], w.z, fmaf(hdec[i+3], w.w, a))));
            }
            q2[tid] = a;
        }
        __syncthreads();
        if (tid < 120) {
            const int head = tid & 7, kk = tid >> 3;
            float s = 0.f;
            const float* kp = Kb + kk * 256 + head * 16;
#pragma unroll
            for (int d = 0; d < 16; d++) s = fmaf(q2[head * 16 + d], kp[d], s);
            s *= 0.25f;
            sc[head * 15 + kk] = valid[kk] ? s : -1e9f;
        }
        __syncthreads();
        if (tid < 8) {
            float mx = -INFINITY;
            for (int kk = 0; kk < KA; kk++) mx = fmaxf(mx, sc[tid * 15 + kk]);
            float ssum = 0.f;
            for (int kk = 0; kk < KA; kk++) {
                const float e = expf(sc[tid * 15 + kk] - mx);
                sc[tid * 15 + kk] = e;
                ssum += e;
            }
            const float inv = 1.0f / ssum;
            for (int kk = 0; kk < KA; kk++) sc[tid * 15 + kk] *= inv;
        }
        __syncthreads();
        if (tid < 128) {
            const int head = tid >> 4, d = tid & 15;
            float o = 0.f;
            for (int kk = 0; kk < KA; kk++)
                o = fmaf(sc[head * 15 + kk], Vb[kk * 128 + head * 16 + d], o);
            odec[tid] = o;
        }
        __syncthreads();
        if (tid < 128) {
            float a = __ldg(p.dbo + tid);
            const float4* wq = reinterpret_cast<const float4*>(g_wt + OFF_DWO) + tid;
            for (int i = 0; i < 128; i += 4) {
                const float4 w = __ldg(wq + (i >> 2) * 128);
                a = fmaf(odec[i], w.x, fmaf(odec[i+1], w.y, fmaf(odec[i+2], w.z, fmaf(odec[i+3], w.w, a))));
            }
            hdec[tid] += a;
        }
        __syncthreads();

        // ---- final pointer layer ----
        if (tid < 128) {
            float a = __ldg(p.dbq + 128 + tid);
            const float4* wq = reinterpret_cast<const float4*>(g_wt + OFF_DWQ + 16384) + tid;
            for (int i = 0; i < 128; i += 4) {
                const float4 w = __ldg(wq + (i >> 2) * 128);
                a = fmaf(hdec[i], w.x, fmaf(hdec[i+1], w.y, fmaf(hdec[i+2], w.z, fmaf(hdec[i+3], w.w, a))));
            }
            q2[tid] = a;
        }
        __syncthreads();
        if (tid < KA) {
            float s = 0.f;
            const float* kp = Kb + tid * 256 + 128;
            for (int d = 0; d < 128; d++) s = fmaf(q2[d], kp[d], s);
            s *= 0.08838834764831845f;
            s = 10.0f * tanhf(s);
            lg[tid] = valid[tid] ? s : -1e9f;
        }
        __syncthreads();
        if (tid == 0) {
            float mx = -INFINITY; int best = 0;
            for (int kk = 0; kk < KA; kk++)
                if (lg[kk] > mx) { mx = lg[kk]; best = kk; }
            float ssum = 0.f, eb = 0.f;
            for (int kk = 0; kk < KA; kk++) {
                const float e = expf(lg[kk] - mx);
                ssum += e;
                if (kk == best) eb = e;
            }
            misc[4] += logf(eb / ssum);
            const int nxt = knn[best];
            mask[nxt] = 0;
            misc[0] = xsx[nxt]; misc[1] = xsy[nxt];
            p.out[b * NN + step + 1] = (float)nxt;
        }
        __syncthreads();
    }

    if (tid == 0) p.out[B * NN + b] = misc[4];
}

extern "C" void kernel_launch(void* const* d_in, const int* in_sizes, int n_in,
                              void* d_out, int out_size)
{
    int i = 2;
    if (n_in > 2 && in_sizes[2] == 1) i = 4;

    const float* aEmbW  = (const float*)d_in[i+0];
    const float* aEmbB  = (const float*)d_in[i+1];
    const float* aAttnW = (const float*)d_in[i+2];
    const float* aAttnB = (const float*)d_in[i+3];
    const float* aW1    = (const float*)d_in[i+4];
    const float* aB1    = (const float*)d_in[i+5];
    const float* aW2    = (const float*)d_in[i+6];
    const float* aB2    = (const float*)d_in[i+7];
    const float* aLn    = (const float*)d_in[i+8];
    const float* sEmbW  = (const float*)d_in[i+9];
    const float* sEmbB  = (const float*)d_in[i+10];
    const float* sAttnW = (const float*)d_in[i+11];
    const float* sAttnB = (const float*)d_in[i+12];
    const float* sW1    = (const float*)d_in[i+13];
    const float* sB1    = (const float*)d_in[i+14];
    const float* sW2    = (const float*)d_in[i+15];
    const float* sB2    = (const float*)d_in[i+16];
    const float* sLn    = (const float*)d_in[i+17];
    const float* WK     = (const float*)d_in[i+18];
    const float* bK     = (const float*)d_in[i+19];
    const float* WV     = (const float*)d_in[i+20];
    const float* bV     = (const float*)d_in[i+21];
    const float* Wqm    = (const float*)d_in[i+22];
    const float* bqm    = (const float*)d_in[i+23];
    const float* dWq    = (const float*)d_in[i+24];
    const float* dbq    = (const float*)d_in[i+25];
    const float* dWo    = (const float*)d_in[i+26];
    const float* dbo    = (const float*)d_in[i+27];

    // prologue: transpose all GEMM weights into quad-interleaved layout
    tq_kernel<<<64, 256>>>(aAttnW, OFF_AATTN, 128, 128, 8);
    tq_kernel<<<64, 256>>>(sAttnW, OFF_SATTN, 128, 128, 8);
    tq_kernel<<<64, 256>>>(aW1,    OFF_AW1,   128, 512, 2);
    tq_kernel<<<64, 256>>>(sW1,    OFF_SW1,   128, 512, 2);
    tq_kernel<<<64, 256>>>(aW2,    OFF_AW2,   512, 128, 2);
    tq_kernel<<<64, 256>>>(sW2,    OFF_SW2,   512, 128, 2);
    tq_kernel<<<64, 256>>>(WK,     OFF_WK,    256, 256, 1);
    tq_kernel<<<64, 256>>>(WV,     OFF_WV,    256, 256, 1);
    tq_kernel<<<64, 256>>>(Wqm,    OFF_WQM,   384, 128, 1);
    tq_kernel<<<64, 256>>>(dWq,    OFF_DWQ,   128, 128, 2);
    tq_kernel<<<64, 256>>>(dWo,    OFF_DWO,   128, 128, 2);

    Params p;
    p.x = (const float*)d_in[0];
    p.start = (const int*)d_in[1];
    p.aEmbW = aEmbW; p.aEmbB = aEmbB; p.aAttnB = aAttnB;
    p.aB1 = aB1; p.aB2 = aB2; p.aLn = aLn;
    p.sEmbW = sEmbW; p.sEmbB = sEmbB; p.sAttnB = sAttnB;
    p.sB1 = sB1; p.sB2 = sB2; p.sLn = sLn;
    p.bK = bK; p.bV = bV; p.bqm = bqm; p.dbq = dbq; p.dbo = dbo;
    p.out = (float*)d_out;

    cudaFuncSetAttribute(tsp_kernel, cudaFuncAttributeMaxDynamicSharedMemorySize, SMEM_BYTES);

    const int B = in_sizes[1];
    tsp_kernel<<<B, NTH, SMEM_BYTES>>>(p);
}